// round 1
// baseline (speedup 1.0000x reference)
#include <cuda_runtime.h>
#include <math.h>

// Problem constants
#define NN 4
#define C1 128
#define C2 36
#define Hh 192
#define Ww 192
#define HO 190
#define WO 190
#define HW (Hh*Ww)
#define HWO (HO*WO)

// Scratch (device globals: allocation-free rule)
__device__ float g_offset[NN*C2*HO*WO];   // offset conv output [N,36,HO,WO]
__device__ float g_wt[9*C1*C2];           // deform_w transposed to [tap][c][o]

// ---------------------------------------------------------------------------
// Prep: transpose deform_w [o][c][3][3] -> g_wt[tap][c][o]
// so the deform kernel can load per-tap weights fully coalesced.
// ---------------------------------------------------------------------------
__global__ void prep_kernel(const float* __restrict__ dw) {
    int idx = blockIdx.x * 256 + threadIdx.x;
    if (idx < 9 * C1 * C2) {
        int t = idx / (C1 * C2);
        int r = idx % (C1 * C2);
        int c = r / C2, o = r % C2;
        g_wt[idx] = dw[(o * C1 + c) * 9 + t];
    }
}

// ---------------------------------------------------------------------------
// Offset-generating grouped conv (groups=4, VALID, 3x3, stride 1)
// Block: 192 threads = 32x6 pixel tile, one (n, group) per blockIdx.z.
// ---------------------------------------------------------------------------
__global__ __launch_bounds__(192) void offset_conv_kernel(
    const float* __restrict__ x, const float* __restrict__ cw)
{
    __shared__ float sx[32 * 8 * 34];   // 32 ch, 8 rows, 34 cols
    __shared__ float ws[32 * 9 * 9];    // [ci][tap][o]

    int n = blockIdx.z >> 2;
    int g = blockIdx.z & 3;
    int x0 = blockIdx.x * 32;
    int y0 = blockIdx.y * 6;
    int tid = threadIdx.x;

    // weights: conv_w[(g*9+o)*32+ci][tap] -> ws[(ci*9+tap)*9+o]
    for (int idx = tid; idx < 2592; idx += 192) {
        int o = idx % 9; int rem = idx / 9;
        int tap = rem % 9; int ci = rem / 9;
        ws[idx] = cw[((g * 9 + o) * 32 + ci) * 9 + tap];
    }

    const float* xb = x + ((size_t)n * C1 + g * 32) * HW;
    for (int idx = tid; idx < 32 * 8 * 34; idx += 192) {
        int ci = idx / 272;
        int r  = (idx % 272) / 34;
        int col = idx % 34;
        int gy = y0 + r, gx = x0 + col;
        float v = 0.f;
        if (gy < Hh && gx < Ww) v = xb[ci * HW + gy * Ww + gx];
        sx[idx] = v;
    }
    __syncthreads();

    int lx = tid & 31, ly = tid >> 5;   // ly in 0..5
    float acc[9];
#pragma unroll
    for (int o = 0; o < 9; o++) acc[o] = 0.f;

    for (int ci = 0; ci < 32; ci++) {
        int base = ci * 272 + ly * 34 + lx;
#pragma unroll
        for (int tap = 0; tap < 9; tap++) {
            int i = tap / 3, j = tap % 3;
            float v = sx[base + i * 34 + j];
            const float* wp = &ws[(ci * 9 + tap) * 9];
#pragma unroll
            for (int o = 0; o < 9; o++) acc[o] = fmaf(v, wp[o], acc[o]);
        }
    }

    int yy = y0 + ly, xx = x0 + lx;
    if (yy < HO && xx < WO) {
        float* op = g_offset + ((size_t)n * C2 + g * 9) * HWO + yy * WO + xx;
#pragma unroll
        for (int o = 0; o < 9; o++) op[o * HWO] = acc[o];
    }
}

// ---------------------------------------------------------------------------
// Deformable conv + BN + Mish.
// One thread per output pixel; 36 fp32 accumulators in registers.
// Per-tap weights staged in smem as [c][36] (float4-aligned: 36*4B = 144B).
// ---------------------------------------------------------------------------
__global__ __launch_bounds__(128, 4) void deform_kernel(
    const float* __restrict__ x,
    const float* __restrict__ gamma, const float* __restrict__ beta,
    const float* __restrict__ mean,  const float* __restrict__ var,
    float* __restrict__ out)
{
    __shared__ float4 wts[1152];   // 4608 floats = [c=128][o=36]

    int n = blockIdx.y;
    int p = blockIdx.x * 128 + threadIdx.x;
    bool active = (p < HWO);
    if (!active) p = HWO - 1;
    int yy = p / WO, xx = p % WO;

    const float* xb = x + (size_t)n * C1 * HW;
    const float* offb = g_offset + (size_t)n * C2 * HWO + yy * WO + xx;
    const float4* gwt4 = (const float4*)g_wt;

    float acc[36];
#pragma unroll
    for (int o = 0; o < 36; o++) acc[o] = 0.f;

    for (int t = 0; t < 9; t++) {
        __syncthreads();
        for (int idx = threadIdx.x; idx < 1152; idx += 128)
            wts[idx] = gwt4[t * 1152 + idx];
        __syncthreads();

        int i = t / 3, j = t % 3;
#pragma unroll
        for (int dg = 0; dg < 2; dg++) {
            float dy = offb[(dg * 18 + t * 2    ) * HWO];
            float dx = offb[(dg * 18 + t * 2 + 1) * HWO];
            float py = (float)(yy + i) + dy;
            float px = (float)(xx + j) + dx;
            float fy0 = floorf(py), fx0 = floorf(px);
            float wy1 = py - fy0, wx1 = px - fx0;
            float wy0 = 1.f - wy1, wx0 = 1.f - wx1;

            bool vy0 = (fy0       >= 0.f) && (fy0       <= (float)(Hh - 1));
            bool vy1 = (fy0 + 1.f >= 0.f) && (fy0 + 1.f <= (float)(Hh - 1));
            bool vx0 = (fx0       >= 0.f) && (fx0       <= (float)(Ww - 1));
            bool vx1 = (fx0 + 1.f >= 0.f) && (fx0 + 1.f <= (float)(Ww - 1));

            int y0i = (int)fy0, x0i = (int)fx0;
            int y0c = min(max(y0i,     0), Hh - 1);
            int y1c = min(max(y0i + 1, 0), Hh - 1);
            int x0c = min(max(x0i,     0), Ww - 1);
            int x1c = min(max(x0i + 1, 0), Ww - 1);

            float W00 = wy0 * wx0 * ((vy0 && vx0) ? 1.f : 0.f);
            float W01 = wy0 * wx1 * ((vy0 && vx1) ? 1.f : 0.f);
            float W10 = wy1 * wx0 * ((vy1 && vx0) ? 1.f : 0.f);
            float W11 = wy1 * wx1 * ((vy1 && vx1) ? 1.f : 0.f);

            int o00 = y0c * Ww + x0c, o01 = y0c * Ww + x1c;
            int o10 = y1c * Ww + x0c, o11 = y1c * Ww + x1c;

            const float*  pc = xb + dg * 64 * HW;
            const float4* wb = wts + dg * 64 * 9;
#pragma unroll 2
            for (int c = 0; c < 64; c++) {
                const float* pp = pc + c * HW;
                float v = W00 * __ldg(pp + o00)
                        + W01 * __ldg(pp + o01)
                        + W10 * __ldg(pp + o10)
                        + W11 * __ldg(pp + o11);
                const float4* wp = wb + c * 9;
#pragma unroll
                for (int q = 0; q < 9; q++) {
                    float4 wv = wp[q];
                    acc[q*4+0] = fmaf(v, wv.x, acc[q*4+0]);
                    acc[q*4+1] = fmaf(v, wv.y, acc[q*4+1]);
                    acc[q*4+2] = fmaf(v, wv.z, acc[q*4+2]);
                    acc[q*4+3] = fmaf(v, wv.w, acc[q*4+3]);
                }
            }
        }
    }

    if (active) {
        float* ob = out + (size_t)n * C2 * HWO + yy * WO + xx;
#pragma unroll
        for (int o = 0; o < 36; o++) {
            float s = __ldg(gamma + o) * rsqrtf(__ldg(var + o) + 1e-5f);
            float b = __ldg(beta + o) - __ldg(mean + o) * s;
            float z = fmaf(acc[o], s, b);
            float sp = (z > 20.f) ? z : log1pf(expf(z));
            ob[o * HWO] = z * tanhf(sp);
        }
    }
}

// ---------------------------------------------------------------------------
extern "C" void kernel_launch(void* const* d_in, const int* in_sizes, int n_in,
                              void* d_out, int out_size)
{
    const float* x        = (const float*)d_in[0];
    const float* conv_w   = (const float*)d_in[1];
    const float* deform_w = (const float*)d_in[2];
    const float* bn_gamma = (const float*)d_in[3];
    const float* bn_beta  = (const float*)d_in[4];
    const float* bn_mean  = (const float*)d_in[5];
    const float* bn_var   = (const float*)d_in[6];
    float* out = (float*)d_out;

    prep_kernel<<<(9 * C1 * C2 + 255) / 256, 256>>>(deform_w);

    // offset conv: tiles of 32x6 pixels, 6 x 32 tiles, 4n * 4g
    offset_conv_kernel<<<dim3(6, 32, 16), 192>>>(x, conv_w);

    // deform conv: 190*190 = 36100 pixels per image, 128 threads/block
    deform_kernel<<<dim3((HWO + 127) / 128, NN), 128>>>(
        x, bn_gamma, bn_beta, bn_mean, bn_var, out);
}